// round 16
// baseline (speedup 1.0000x reference)
#include <cuda_runtime.h>
#include <cuda_fp16.h>
#include <cstdint>

#define N_NODES 100000
#define FEATS   256
#define N_EDGES 3200000
#define CAP     128          // neighbor bucket capacity (Poisson(32): 17-sigma margin)

// Scratch (allocation-free rule: __device__ globals)
__device__ __half g_h[(long long)N_NODES * FEATS];    // linear output h (fp16, 51 MB)
__device__ int    g_idx_is64;                         // 1 if edge_index is int64
__device__ int    g_cnt[N_NODES];                     // per-dest degree (atomic cursors)
__device__ int    g_col[(long long)N_NODES * CAP];    // bucketed neighbor lists (51 MB)

// ---------------------------------------------------------------------------
// zero counts + (block 0) detect edge_index dtype
// ---------------------------------------------------------------------------
__global__ void zero_detect_kernel(const int* __restrict__ ei_words) {
    int i = blockIdx.x * blockDim.x + threadIdx.x;
    if (i < N_NODES) g_cnt[i] = 0;
    if (blockIdx.x == 0 && threadIdx.x < 128) {
        __shared__ int nz;
        if (threadIdx.x == 0) nz = 0;
        __syncthreads();
        int w = ei_words[1 + 2 * threadIdx.x];
        if (w != 0) atomicAdd(&nz, 1);
        __syncthreads();
        if (threadIdx.x == 0) g_idx_is64 = (nz == 0);
    }
}

__device__ __forceinline__ void load_edge(const void* ei, long long e, int& r, int& c) {
    if (g_idx_is64) {
        r = (int)((const long long*)ei)[e];
        c = (int)((const long long*)ei)[N_EDGES + e];
    } else {
        r = ((const int*)ei)[e];
        c = ((const int*)ei)[N_EDGES + e];
    }
}

// ---------------------------------------------------------------------------
// Bucket fill: 4-way unrolled so 4 independent atomics are in flight/thread.
// ---------------------------------------------------------------------------
#define FILL_GRID 1024

__global__ __launch_bounds__(256) void fill_kernel(const void* __restrict__ ei) {
    const long long t = (long long)blockIdx.x * blockDim.x + threadIdx.x;
    const long long stride = (long long)FILL_GRID * 256;

    long long e = t;
    for (; e + 3 * stride < N_EDGES; e += 4 * stride) {
        int r[4], c[4];
        #pragma unroll
        for (int j = 0; j < 4; j++)
            load_edge(ei, e + j * stride, r[j], c[j]);
        #pragma unroll
        for (int j = 0; j < 4; j++) {
            if ((unsigned)r[j] < N_NODES && (unsigned)c[j] < N_NODES) {
                int pos = atomicAdd(&g_cnt[r[j]], 1);
                if (pos < CAP)
                    g_col[(long long)r[j] * CAP + pos] = c[j];
            }
        }
    }
    for (; e < N_EDGES; e += stride) {
        int r, c;
        load_edge(ei, e, r, c);
        if ((unsigned)r >= N_NODES || (unsigned)c >= N_NODES) continue;
        int pos = atomicAdd(&g_cnt[r], 1);
        if (pos < CAP)
            g_col[(long long)r * CAP + pos] = c;
    }
}

// ---------------------------------------------------------------------------
// Persistent fp16 GEMM, whole-tile staging:
//   - full W (256x256) fp16 in smem once per block (135 KB)
//   - full A row-tile (128x256) fp16 staged per tile (67 KB) in one burst
//   - mma sweep over K=256 with NO intra-tile barriers
// 148 blocks x 512 threads (16 warps: 4m x 4n, warp tile 32x64).
// ---------------------------------------------------------------------------
#define GBM 128
#define APITCH 264              // halves; 132 words/row -> conflict-free frags
#define BPITCH 264
#define GTILES ((N_NODES + GBM - 1) / GBM)   // 782
#define GEMM_BLOCKS 148
#define GEMM_THREADS 512
#define GEMM_SMEM (GBM * APITCH * 2 + 256 * BPITCH * 2)   // 67584+135168 = 202752

__device__ __forceinline__ void mma_f16(float* c, uint32_t a0, uint32_t a1,
                                        uint32_t a2, uint32_t a3,
                                        uint32_t b0, uint32_t b1) {
    asm volatile(
        "mma.sync.aligned.m16n8k16.row.col.f32.f16.f16.f32 "
        "{%0,%1,%2,%3}, {%4,%5,%6,%7}, {%8,%9}, {%0,%1,%2,%3};"
        : "+f"(c[0]), "+f"(c[1]), "+f"(c[2]), "+f"(c[3])
        : "r"(a0), "r"(a1), "r"(a2), "r"(a3), "r"(b0), "r"(b1));
}

__global__ __launch_bounds__(GEMM_THREADS) void gemm_kernel(const float* __restrict__ A,
                                                            const float* __restrict__ W,
                                                            const float* __restrict__ bias) {
    extern __shared__ __half smem[];
    __half (*As)[APITCH] = reinterpret_cast<__half(*)[APITCH]>(smem);
    __half (*Bs)[BPITCH] = reinterpret_cast<__half(*)[BPITCH]>(smem + GBM * APITCH);

    const int tid = threadIdx.x;
    const int warp = tid >> 5;
    const int lane = tid & 31;
    const int wm = (warp & 3) * 32;      // 4 row groups of 32
    const int wn = (warp >> 2) * 64;     // 4 col groups of 64
    const int grp = lane >> 2;
    const int tig = lane & 3;

    // --- W preload: 256x256 fp32 -> Bs[n][k] fp16, once per block ---
    {
        int n  = tid & 255;
        int kh = (tid >> 8) * 128;
        for (int j = 0; j < 64; j++) {
            int k = kh + 2 * j;
            float w0 = __ldg(&W[(long long)k * FEATS + n]);
            float w1 = __ldg(&W[(long long)(k + 1) * FEATS + n]);
            *reinterpret_cast<__half2*>(&Bs[n][k]) = __floats2half2_rn(w0, w1);
        }
    }
    __syncthreads();

    for (int tile = blockIdx.x; tile < GTILES; tile += gridDim.x) {
        const int rowBase = tile * GBM;

        // --- Stage full A tile: 128 rows x 256 floats = 8192 float4, 16/thread,
        //     in two 8-deep MLP batches, converted to fp16 on store. ---
        #pragma unroll
        for (int s = 0; s < 16; s += 8) {
            float4 v[8];
            #pragma unroll
            for (int j = 0; j < 8; j++) {
                int idx = tid + (s + j) * GEMM_THREADS;
                int ar = idx >> 6;               // 64 float4 per row
                int ac4 = (idx & 63) * 4;
                int grow = rowBase + ar;
                v[j] = make_float4(0.f, 0.f, 0.f, 0.f);
                if (grow < N_NODES)
                    v[j] = *reinterpret_cast<const float4*>(A + (long long)grow * FEATS + ac4);
            }
            #pragma unroll
            for (int j = 0; j < 8; j++) {
                int idx = tid + (s + j) * GEMM_THREADS;
                int ar = idx >> 6;
                int ac4 = (idx & 63) * 4;
                __half2* ap = reinterpret_cast<__half2*>(&As[ar][ac4]);
                ap[0] = __floats2half2_rn(v[j].x, v[j].y);
                ap[1] = __floats2half2_rn(v[j].z, v[j].w);
            }
        }
        __syncthreads();

        // --- MMA sweep: K=256, no barriers ---
        float acc[2][8][4];
        #pragma unroll
        for (int i = 0; i < 2; i++)
            #pragma unroll
            for (int j = 0; j < 8; j++)
                #pragma unroll
                for (int k = 0; k < 4; k++) acc[i][j][k] = 0.f;

        #pragma unroll 4
        for (int ks = 0; ks < FEATS; ks += 16) {
            uint32_t afr[2][4];
            #pragma unroll
            for (int mi = 0; mi < 2; mi++) {
                int m = wm + mi * 16 + grp;
                afr[mi][0] = *reinterpret_cast<const uint32_t*>(&As[m][ks + 2 * tig]);
                afr[mi][1] = *reinterpret_cast<const uint32_t*>(&As[m + 8][ks + 2 * tig]);
                afr[mi][2] = *reinterpret_cast<const uint32_t*>(&As[m][ks + 2 * tig + 8]);
                afr[mi][3] = *reinterpret_cast<const uint32_t*>(&As[m + 8][ks + 2 * tig + 8]);
            }
            uint32_t bfr[8][2];
            #pragma unroll
            for (int ni = 0; ni < 8; ni++) {
                int n = wn + ni * 8 + grp;
                bfr[ni][0] = *reinterpret_cast<const uint32_t*>(&Bs[n][ks + 2 * tig]);
                bfr[ni][1] = *reinterpret_cast<const uint32_t*>(&Bs[n][ks + 2 * tig + 8]);
            }
            #pragma unroll
            for (int mi = 0; mi < 2; mi++)
                #pragma unroll
                for (int ni = 0; ni < 8; ni++)
                    mma_f16(acc[mi][ni], afr[mi][0], afr[mi][1], afr[mi][2], afr[mi][3],
                            bfr[ni][0], bfr[ni][1]);
        }

        // --- Epilogue: add bias, write g_h fp16 ---
        #pragma unroll
        for (int mi = 0; mi < 2; mi++) {
            int row0 = rowBase + wm + mi * 16 + grp;
            int row1 = row0 + 8;
            #pragma unroll
            for (int ni = 0; ni < 8; ni++) {
                int col = wn + ni * 8 + 2 * tig;
                float b0 = __ldg(&bias[col]);
                float b1 = __ldg(&bias[col + 1]);
                if (row0 < N_NODES) {
                    __half2 v = __floats2half2_rn(acc[mi][ni][0] + b0, acc[mi][ni][1] + b1);
                    *reinterpret_cast<__half2*>(g_h + (long long)row0 * FEATS + col) = v;
                }
                if (row1 < N_NODES) {
                    __half2 v = __floats2half2_rn(acc[mi][ni][2] + b0, acc[mi][ni][3] + b1);
                    *reinterpret_cast<__half2*>(g_h + (long long)row1 * FEATS + col) = v;
                }
            }
        }
        __syncthreads();   // protect As before next tile's staging
    }
}

// ---------------------------------------------------------------------------
// Gather-sum (R11 exact): one warp per node; lane owns 8 feats (uint4 fp16).
// ---------------------------------------------------------------------------
__device__ __forceinline__ void acc_uint4_h8(float* acc, uint4 v) {
    const __half2* hp = reinterpret_cast<const __half2*>(&v);
    #pragma unroll
    for (int q = 0; q < 4; q++) {
        float2 f = __half22float2(hp[q]);
        acc[2 * q]     += f.x;
        acc[2 * q + 1] += f.y;
    }
}

__global__ __launch_bounds__(256) void gather_kernel(float* __restrict__ out) {
    int node = blockIdx.x * 8 + (threadIdx.x >> 5);
    int lane = threadIdx.x & 31;
    if (node >= N_NODES) return;

    int deg = g_cnt[node];
    int n = deg < CAP ? deg : CAP;   // clamp (overflow statistically impossible)
    const int* __restrict__ cols = g_col + (long long)node * CAP;

    float acc[8] = {0.f, 0.f, 0.f, 0.f, 0.f, 0.f, 0.f, 0.f};

    int i = 0;
    for (; i + 3 < n; i += 4) {
        int c0 = __ldg(&cols[i]);
        int c1 = __ldg(&cols[i + 1]);
        int c2 = __ldg(&cols[i + 2]);
        int c3 = __ldg(&cols[i + 3]);
        uint4 v0 = __ldg(reinterpret_cast<const uint4*>(g_h + (long long)c0 * FEATS) + lane);
        uint4 v1 = __ldg(reinterpret_cast<const uint4*>(g_h + (long long)c1 * FEATS) + lane);
        uint4 v2 = __ldg(reinterpret_cast<const uint4*>(g_h + (long long)c2 * FEATS) + lane);
        uint4 v3 = __ldg(reinterpret_cast<const uint4*>(g_h + (long long)c3 * FEATS) + lane);
        acc_uint4_h8(acc, v0);
        acc_uint4_h8(acc, v1);
        acc_uint4_h8(acc, v2);
        acc_uint4_h8(acc, v3);
    }
    for (; i < n; i++) {
        int c0 = __ldg(&cols[i]);
        uint4 v0 = __ldg(reinterpret_cast<const uint4*>(g_h + (long long)c0 * FEATS) + lane);
        acc_uint4_h8(acc, v0);
    }

    float inv = deg > 0 ? 1.0f / (float)deg : 0.f;
    #pragma unroll
    for (int q = 0; q < 8; q++) acc[q] *= inv;

    float* dst = out + (long long)node * FEATS + lane * 8;
    float4 o0 = make_float4(acc[0], acc[1], acc[2], acc[3]);
    float4 o1 = make_float4(acc[4], acc[5], acc[6], acc[7]);
    __stcs(reinterpret_cast<float4*>(dst), o0);
    __stcs(reinterpret_cast<float4*>(dst) + 1, o1);
}

// ---------------------------------------------------------------------------
extern "C" void kernel_launch(void* const* d_in, const int* in_sizes, int n_in,
                              void* d_out, int out_size) {
    const float* x  = (const float*)d_in[0];
    const void*  ei = d_in[1];
    const float* W  = (const float*)d_in[2];
    const float* b  = (const float*)d_in[3];
    float* out = (float*)d_out;

    cudaFuncSetAttribute(gemm_kernel, cudaFuncAttributeMaxDynamicSharedMemorySize,
                         GEMM_SMEM);

    zero_detect_kernel<<<(N_NODES + 255) / 256, 256>>>((const int*)ei);
    fill_kernel<<<FILL_GRID, 256>>>(ei);
    gemm_kernel<<<GEMM_BLOCKS, GEMM_THREADS, GEMM_SMEM>>>(x, W, b);
    gather_kernel<<<(N_NODES + 7) / 8, 256>>>(out);
}